// round 2
// baseline (speedup 1.0000x reference)
#include <cuda_runtime.h>
#include <math.h>

// Shapes
#define BB   64
#define NN   128
#define EE   256
#define DD   256
#define HH   8
#define HD_  32
#define MT   384   // N + E
#define NT   129   // N + 1

// ---------------- scratch (device globals; no allocation) ----------------
__device__ float g_qkv [BB*NN*3*DD];   // node qkv projections
__device__ float g_kve [BB*EE*2*DD];   // edge k,v projections
__device__ float g_attn[BB*NN*DD];
__device__ float g_x1  [BB*NN*DD];
__device__ float g_h1  [BB*NN*DD];
__device__ float g_ff  [BB*NN*DD];
__device__ float g_tok [BB*NT*DD];
__device__ float g_rkv [BB*NT*2*DD];
__device__ float g_cls2[BB*DD];
__device__ float g_c1  [BB*DD];
__device__ float g_ch1 [BB*DD];
__device__ float g_cff [BB*DD];

// ---------------- GEMM: C[M,Nc] = A[M,256] @ W (+bias, relu) -------------
// TRANSB=false: W is [K, Nc] row-major  (out = A @ W)
// TRANSB=true : W is [Nc, K] row-major  (out = A @ W^T)
// Tile: BM=128, BN=64, BK=16; 256 threads; 8x4 micro-tile per thread.
template<bool TRANSB, bool RELU>
__global__ void gemm_kernel(const float* __restrict__ A,
                            const float* __restrict__ W,
                            const float* __restrict__ bias,
                            float* __restrict__ C,
                            int M, int Nc) {
    const int K = 256;
    __shared__ float As[16][132];   // [k][m], row stride 132 floats (16B aligned)
    __shared__ float Ws[16][68];    // [k][n]

    int tid = threadIdx.x;
    int tx = tid & 15;      // n dir
    int ty = tid >> 4;      // m dir
    int m0 = blockIdx.y * 128;
    int n0 = blockIdx.x * 64;

    float acc[8][4];
#pragma unroll
    for (int i = 0; i < 8; i++)
#pragma unroll
        for (int j = 0; j < 4; j++) acc[i][j] = 0.f;

    for (int k0 = 0; k0 < K; k0 += 16) {
        // load A tile 128x16 (2 float4 per thread)
        {
            int r  = tid >> 1;
            int kk = (tid & 1) * 8;
            float4 v0, v1;
            if (m0 + r < M) {
                const float* p = A + (size_t)(m0 + r) * K + k0 + kk;
                v0 = *(const float4*)p;
                v1 = *(const float4*)(p + 4);
            } else {
                v0 = make_float4(0.f, 0.f, 0.f, 0.f);
                v1 = v0;
            }
            As[kk + 0][r] = v0.x; As[kk + 1][r] = v0.y;
            As[kk + 2][r] = v0.z; As[kk + 3][r] = v0.w;
            As[kk + 4][r] = v1.x; As[kk + 5][r] = v1.y;
            As[kk + 6][r] = v1.z; As[kk + 7][r] = v1.w;
        }
        // load W tile 16x64
        if (!TRANSB) {
            int kr = tid >> 4;          // 0..15
            int n  = (tid & 15) * 4;
            float4 v = *(const float4*)(W + (size_t)(k0 + kr) * Nc + n0 + n);
            *(float4*)&Ws[kr][n] = v;
        } else {
            int n  = tid >> 2;          // 0..63
            int kk = (tid & 3) * 4;
            float4 v = *(const float4*)(W + (size_t)(n0 + n) * K + k0 + kk);
            Ws[kk + 0][n] = v.x; Ws[kk + 1][n] = v.y;
            Ws[kk + 2][n] = v.z; Ws[kk + 3][n] = v.w;
        }
        __syncthreads();

#pragma unroll
        for (int k = 0; k < 16; k++) {
            float4 a0 = *(float4*)&As[k][ty * 8];
            float4 a1 = *(float4*)&As[k][ty * 8 + 4];
            float4 w  = *(float4*)&Ws[k][tx * 4];
            float ar[8] = {a0.x, a0.y, a0.z, a0.w, a1.x, a1.y, a1.z, a1.w};
            float wr[4] = {w.x, w.y, w.z, w.w};
#pragma unroll
            for (int i = 0; i < 8; i++)
#pragma unroll
                for (int j = 0; j < 4; j++)
                    acc[i][j] = fmaf(ar[i], wr[j], acc[i][j]);
        }
        __syncthreads();
    }

#pragma unroll
    for (int i = 0; i < 8; i++) {
        int row = m0 + ty * 8 + i;
        if (row < M) {
#pragma unroll
            for (int j = 0; j < 4; j++) {
                int col = n0 + tx * 4 + j;
                float v = acc[i][j] + bias[col];
                if (RELU) v = fmaxf(v, 0.f);
                C[(size_t)row * Nc + col] = v;
            }
        }
    }
}

// ---------------- node attention: one block per (h, b) -------------------
// K/V for all 384 tokens of this (b,h) staged in SMEM; warp per query row.
__global__ void attn_kernel(const float* __restrict__ qkv,
                            const float* __restrict__ kve,
                            const unsigned char* __restrict__ nmask,
                            float* __restrict__ out) {
    int h = blockIdx.x, b = blockIdx.y;
    extern __shared__ float sm[];
    float* Ks = sm;                  // 384*33
    float* Vs = Ks + MT * 33;        // 384*33
    float* sp = Vs + MT * 33;        // 8*384
    float* sq = sp + 8 * MT;         // 8*32

    int tid = threadIdx.x;
    // stage K and V
    for (int idx = tid; idx < MT * 32; idx += 256) {
        int m = idx >> 5, d = idx & 31;
        float kv, vv;
        if (m < NN) {
            const float* base = qkv + (size_t)(b * NN + m) * 768 + h * 32 + d;
            kv = base[256];            // k_n at offset D
            vv = base[512];            // v_n at offset 2D
        } else {
            const float* base = kve + (size_t)(b * EE + (m - NN)) * 512 + h * 32 + d;
            kv = base[0];              // k_e
            vv = base[256];            // v_e at offset D
        }
        Ks[m * 33 + d] = kv;
        Vs[m * 33 + d] = vv;
    }
    __syncthreads();

    int w = tid >> 5, lane = tid & 31;
    const float scale = 0.17677669529663687f;   // 32^-0.5
    float* sqh = sq + w * 32;
    float* sph = sp + w * MT;

    for (int n = w; n < NN; n += 8) {
        sqh[lane] = qkv[(size_t)(b * NN + n) * 768 + h * 32 + lane];
        __syncwarp();
        const unsigned char* mrow = nmask + (size_t)(b * NN + n) * MT;

        float svals[12];
        float smax = -INFINITY;
#pragma unroll
        for (int j = 0; j < 12; j++) {
            int m = lane + j * 32;
            const float* kr = Ks + m * 33;
            float s0 = 0.f, s1 = 0.f, s2 = 0.f, s3 = 0.f;
#pragma unroll
            for (int d = 0; d < 32; d += 4) {
                s0 = fmaf(sqh[d    ], kr[d    ], s0);
                s1 = fmaf(sqh[d + 1], kr[d + 1], s1);
                s2 = fmaf(sqh[d + 2], kr[d + 2], s2);
                s3 = fmaf(sqh[d + 3], kr[d + 3], s3);
            }
            float s = ((s0 + s1) + (s2 + s3)) * scale;
            if (mrow[m]) s = -INFINITY;
            svals[j] = s;
            smax = fmaxf(smax, s);
        }
#pragma unroll
        for (int o = 16; o; o >>= 1)
            smax = fmaxf(smax, __shfl_xor_sync(0xffffffffu, smax, o));

        float ssum = 0.f;
#pragma unroll
        for (int j = 0; j < 12; j++) {
            float p = __expf(svals[j] - smax);
            ssum += p;
            sph[lane + j * 32] = p;
        }
#pragma unroll
        for (int o = 16; o; o >>= 1)
            ssum += __shfl_xor_sync(0xffffffffu, ssum, o);
        __syncwarp();

        float inv = 1.f / ssum;
        float a0 = 0.f, a1 = 0.f, a2 = 0.f, a3 = 0.f;
#pragma unroll 4
        for (int m = 0; m < MT; m += 4) {
            a0 = fmaf(sph[m    ], Vs[(m    ) * 33 + lane], a0);
            a1 = fmaf(sph[m + 1], Vs[(m + 1) * 33 + lane], a1);
            a2 = fmaf(sph[m + 2], Vs[(m + 2) * 33 + lane], a2);
            a3 = fmaf(sph[m + 3], Vs[(m + 3) * 33 + lane], a3);
        }
        out[(size_t)(b * NN + n) * DD + h * 32 + lane] = ((a0 + a1) + (a2 + a3)) * inv;
        __syncwarp();
    }
}

// ---------------- LayerNorm over last dim (256), one block per row -------
__global__ void ln_kernel(const float* __restrict__ A,
                          const float* __restrict__ Badd,
                          const float* __restrict__ g,
                          const float* __restrict__ be,
                          float* __restrict__ out) {
    __shared__ float scratch[8];
    int row = blockIdx.x, t = threadIdx.x;
    size_t base = (size_t)row * DD;
    float v = A[base + t] + Badd[base + t];

    float s = v;
#pragma unroll
    for (int o = 16; o; o >>= 1) s += __shfl_xor_sync(0xffffffffu, s, o);
    if ((t & 31) == 0) scratch[t >> 5] = s;
    __syncthreads();
    float tot = 0.f;
#pragma unroll
    for (int i = 0; i < 8; i++) tot += scratch[i];
    float mean = tot * (1.f / 256.f);
    float d = v - mean;
    __syncthreads();

    s = d * d;
#pragma unroll
    for (int o = 16; o; o >>= 1) s += __shfl_xor_sync(0xffffffffu, s, o);
    if ((t & 31) == 0) scratch[t >> 5] = s;
    __syncthreads();
    float tot2 = 0.f;
#pragma unroll
    for (int i = 0; i < 8; i++) tot2 += scratch[i];
    float var = tot2 * (1.f / 256.f);

    out[base + t] = d * rsqrtf(var + 1e-5f) * g[t] + be[t];
}

// ---------------- assemble tok = [CLS; x] --------------------------------
__global__ void tok_kernel(const float* __restrict__ CLS,
                           const float* __restrict__ x,
                           float* __restrict__ tok) {
    int r = blockIdx.x;           // 0 .. 64*129-1
    int b = r / NT, t = r % NT;
    int c = threadIdx.x;
    tok[(size_t)r * DD + c] = (t == 0)
        ? CLS[(size_t)b * DD + c]
        : x[(size_t)(b * NN + (t - 1)) * DD + c];
}

// ---------------- CLS attention: one block per b, warp per head ----------
__global__ void cls_attn_kernel(const float* __restrict__ CLS,
                                const float* __restrict__ rkv,
                                const unsigned char* __restrict__ cmask,
                                float* __restrict__ cls2) {
    int b = blockIdx.x;
    __shared__ float sq[8 * 32];
    __shared__ float sp[8 * 160];
    int tid = threadIdx.x, h = tid >> 5, lane = tid & 31;

    sq[h * 32 + lane] = CLS[(size_t)b * DD + h * 32 + lane];
    __syncwarp();
    const float scale = 0.17677669529663687f;
    const float* sqh = sq + h * 32;

    float svals[5];
    float smax = -INFINITY;
#pragma unroll
    for (int j = 0; j < 5; j++) {
        int m = lane + j * 32;
        float s = -INFINITY;
        if (m < NT) {
            const float* kr = rkv + (size_t)(b * NT + m) * 512 + h * 32;
            float s0 = 0.f, s1 = 0.f, s2 = 0.f, s3 = 0.f;
#pragma unroll
            for (int d = 0; d < 32; d += 4) {
                s0 = fmaf(sqh[d    ], kr[d    ], s0);
                s1 = fmaf(sqh[d + 1], kr[d + 1], s1);
                s2 = fmaf(sqh[d + 2], kr[d + 2], s2);
                s3 = fmaf(sqh[d + 3], kr[d + 3], s3);
            }
            s = ((s0 + s1) + (s2 + s3)) * scale;
            if (cmask[(size_t)b * NT + m]) s = -INFINITY;
        }
        svals[j] = s;
        smax = fmaxf(smax, s);
    }
#pragma unroll
    for (int o = 16; o; o >>= 1)
        smax = fmaxf(smax, __shfl_xor_sync(0xffffffffu, smax, o));

    float ssum = 0.f;
#pragma unroll
    for (int j = 0; j < 5; j++) {
        float p = __expf(svals[j] - smax);    // -inf -> 0
        ssum += p;
        sp[h * 160 + lane + j * 32] = p;
    }
#pragma unroll
    for (int o = 16; o; o >>= 1)
        ssum += __shfl_xor_sync(0xffffffffu, ssum, o);
    __syncwarp();

    float inv = 1.f / ssum;
    float acc = 0.f;
    for (int m = 0; m < NT; m++)
        acc = fmaf(sp[h * 160 + m],
                   rkv[(size_t)(b * NT + m) * 512 + 256 + h * 32 + lane], acc);
    cls2[(size_t)b * DD + h * 32 + lane] = acc * inv;
}

// ---------------- launch --------------------------------------------------
extern "C" void kernel_launch(void* const* d_in, const int* in_sizes, int n_in,
                              void* d_out, int out_size) {
    const float* node_x   = (const float*)d_in[0];
    const float* edge_x   = (const float*)d_in[1];
    const float* CLS      = (const float*)d_in[2];
    const unsigned char* nmask = (const unsigned char*)d_in[3];
    const unsigned char* cmask = (const unsigned char*)d_in[4];
    const float* w_qkv    = (const float*)d_in[5];
    const float* b_qkv    = (const float*)d_in[6];
    const float* w_kve    = (const float*)d_in[7];
    const float* b_kve    = (const float*)d_in[8];
    const float* w1       = (const float*)d_in[9];
    const float* b1       = (const float*)d_in[10];
    const float* w2       = (const float*)d_in[11];
    const float* b2       = (const float*)d_in[12];
    const float* g1       = (const float*)d_in[13];
    const float* be1      = (const float*)d_in[14];
    const float* g2       = (const float*)d_in[15];
    const float* be2      = (const float*)d_in[16];
    const float* ro_w_kv  = (const float*)d_in[17];
    const float* ro_b_kv  = (const float*)d_in[18];
    const float* ro_w1    = (const float*)d_in[19];
    const float* ro_b1    = (const float*)d_in[20];
    const float* ro_w2    = (const float*)d_in[21];
    const float* ro_b2    = (const float*)d_in[22];
    const float* ro_g1    = (const float*)d_in[23];
    const float* ro_be1   = (const float*)d_in[24];
    const float* ro_g2    = (const float*)d_in[25];
    const float* ro_be2   = (const float*)d_in[26];

    float* out_x = (float*)d_out;
    float* out_c = out_x + (size_t)BB * NN * DD;

    float *p_qkv, *p_kve, *p_attn, *p_x1, *p_h1, *p_ff, *p_tok, *p_rkv;
    float *p_cls2, *p_c1, *p_ch1, *p_cff;
    cudaGetSymbolAddress((void**)&p_qkv,  g_qkv);
    cudaGetSymbolAddress((void**)&p_kve,  g_kve);
    cudaGetSymbolAddress((void**)&p_attn, g_attn);
    cudaGetSymbolAddress((void**)&p_x1,   g_x1);
    cudaGetSymbolAddress((void**)&p_h1,   g_h1);
    cudaGetSymbolAddress((void**)&p_ff,   g_ff);
    cudaGetSymbolAddress((void**)&p_tok,  g_tok);
    cudaGetSymbolAddress((void**)&p_rkv,  g_rkv);
    cudaGetSymbolAddress((void**)&p_cls2, g_cls2);
    cudaGetSymbolAddress((void**)&p_c1,   g_c1);
    cudaGetSymbolAddress((void**)&p_ch1,  g_ch1);
    cudaGetSymbolAddress((void**)&p_cff,  g_cff);

    // node qkv: [8192,256] @ [256,768]
    gemm_kernel<false, false><<<dim3(12, 64), 256>>>(node_x, w_qkv, b_qkv, p_qkv, BB * NN, 768);
    // edge kv: [16384,256] @ [256,512]
    gemm_kernel<false, false><<<dim3(8, 128), 256>>>(edge_x, w_kve, b_kve, p_kve, BB * EE, 512);

    // attention
    int attn_smem = (MT * 33 * 2 + 8 * MT + 8 * 32) * (int)sizeof(float);  // 114688 B
    cudaFuncSetAttribute(attn_kernel, cudaFuncAttributeMaxDynamicSharedMemorySize, attn_smem);
    attn_kernel<<<dim3(HH, BB), 256, attn_smem>>>(p_qkv, p_kve, nmask, p_attn);

    // x1 = LN(node_x + attn)
    ln_kernel<<<BB * NN, 256>>>(node_x, p_attn, g1, be1, p_x1);
    // ffn
    gemm_kernel<true, true ><<<dim3(4, 64), 256>>>(p_x1, w1, b1, p_h1, BB * NN, 256);
    gemm_kernel<true, false><<<dim3(4, 64), 256>>>(p_h1, w2, b2, p_ff, BB * NN, 256);
    // x = LN(x1 + ff) -> first output
    ln_kernel<<<BB * NN, 256>>>(p_x1, p_ff, g2, be2, out_x);

    // readout
    tok_kernel<<<BB * NT, 256>>>(CLS, out_x, p_tok);
    gemm_kernel<false, false><<<dim3(8, 65), 256>>>(p_tok, ro_w_kv, ro_b_kv, p_rkv, BB * NT, 512);
    cls_attn_kernel<<<BB, 256>>>(CLS, p_rkv, cmask, p_cls2);
    ln_kernel<<<BB, 256>>>(CLS, p_cls2, ro_g1, ro_be1, p_c1);
    gemm_kernel<true, true ><<<dim3(4, 1), 256>>>(p_c1, ro_w1, ro_b1, p_ch1, BB, 256);
    gemm_kernel<true, false><<<dim3(4, 1), 256>>>(p_ch1, ro_w2, ro_b2, p_cff, BB, 256);
    ln_kernel<<<BB, 256>>>(p_c1, p_cff, ro_g2, ro_be2, out_c);
}

// round 3
// speedup vs baseline: 1.4359x; 1.4359x over previous
#include <cuda_runtime.h>
#include <cuda_bf16.h>
#include <math.h>

// Shapes
#define BB   64
#define NN   128
#define EE   256
#define DD   256
#define HH   8
#define MT   384   // N + E
#define NT   129   // N + 1

// ---------------- scratch (device globals; no allocation) ----------------
__device__ float g_qkv [BB*NN*3*DD];
__device__ float g_kve [BB*EE*2*DD];
__device__ float g_attn[BB*NN*DD];
__device__ float g_x1  [BB*NN*DD];
__device__ float g_h1  [BB*NN*DD];
__device__ float g_ff  [BB*NN*DD];
__device__ float g_tok [BB*NT*DD];
__device__ float g_rkv [BB*NT*2*DD];
__device__ float g_cls2[BB*DD];
__device__ float g_c1  [BB*DD];
__device__ float g_ch1 [BB*DD];
__device__ float g_cff [BB*DD];

// bf16 hi/lo weight buffers, layout [Nc][256] (k contiguous)
#define OFF_QKV   0
#define OFF_KVE   (OFF_QKV + 768*256)
#define OFF_W1    (OFF_KVE + 512*256)
#define OFF_W2    (OFF_W1  + 256*256)
#define OFF_ROKV  (OFF_W2  + 256*256)
#define OFF_ROW1  (OFF_ROKV+ 512*256)
#define OFF_ROW2  (OFF_ROW1+ 256*256)
#define W_TOTAL   (OFF_ROW2+ 256*256)
__device__ __nv_bfloat16 g_whi[W_TOTAL];
__device__ __nv_bfloat16 g_wlo[W_TOTAL];

// ---------------- weight conversion: fp32 -> bf16 hi/lo, [Nc][256] -------
// DIRECT=true : src is [Nc,256] row-major (used as A@W^T)
// DIRECT=false: src is [256,Nc] row-major (used as A@W) -> transpose
template<bool DIRECT>
__global__ void conv_w(const float* __restrict__ W,
                       __nv_bfloat16* __restrict__ hi,
                       __nv_bfloat16* __restrict__ lo, int Nc) {
    int i = blockIdx.x * 256 + threadIdx.x;
    if (i >= Nc * 256) return;
    int n = i >> 8, k = i & 255;
    float v = DIRECT ? W[(size_t)n * 256 + k] : W[(size_t)k * Nc + n];
    __nv_bfloat16 h = __float2bfloat16(v);
    float r = v - __bfloat162float(h);
    hi[i] = h;
    lo[i] = __float2bfloat16(r);
}

// ---------------- bf16-split tensor-core GEMM ----------------------------
// C[M,Nc] = A[M,256] (fp32) @ Whi/Wlo^T ([Nc][256] bf16) + bias (+relu)
// Block 128x128, KC=64, 256 threads (8 warps as 2x4), warp tile 64x32.
__device__ __forceinline__ void mma_bf16(float* c, const unsigned* a, const unsigned* b) {
    asm volatile(
        "mma.sync.aligned.m16n8k16.row.col.f32.bf16.bf16.f32 "
        "{%0,%1,%2,%3}, {%4,%5,%6,%7}, {%8,%9}, {%0,%1,%2,%3};\n"
        : "+f"(c[0]), "+f"(c[1]), "+f"(c[2]), "+f"(c[3])
        : "r"(a[0]), "r"(a[1]), "r"(a[2]), "r"(a[3]), "r"(b[0]), "r"(b[1]));
}

#define GST 72   // smem row stride in bf16 (64 data + 8 pad)

template<bool RELU>
__global__ void __launch_bounds__(256)
gemm_mma(const float* __restrict__ A,
         const __nv_bfloat16* __restrict__ Whi,
         const __nv_bfloat16* __restrict__ Wlo,
         const float* __restrict__ bias,
         float* __restrict__ C, int M, int Nc) {
    extern __shared__ __nv_bfloat16 sm[];
    __nv_bfloat16* sAhi = sm;
    __nv_bfloat16* sAlo = sAhi + 128 * GST;
    __nv_bfloat16* sBhi = sAlo + 128 * GST;
    __nv_bfloat16* sBlo = sBhi + 128 * GST;

    int tid = threadIdx.x;
    int lane = tid & 31, warp = tid >> 5;
    int g = lane >> 2, tq = lane & 3;
    int mbase = (warp >> 2) * 64;    // 0 or 64
    int nbase = (warp & 3) * 32;     // 0,32,64,96
    int m0 = blockIdx.y * 128;
    int n0 = blockIdx.x * 128;

    float acc[4][4][4];
#pragma unroll
    for (int mt = 0; mt < 4; mt++)
#pragma unroll
        for (int nt = 0; nt < 4; nt++)
#pragma unroll
            for (int i = 0; i < 4; i++) acc[mt][nt][i] = 0.f;

    for (int k0 = 0; k0 < 256; k0 += 64) {
        // stage A (fp32 -> hi/lo bf16)
        {
            int r = tid >> 1, half = tid & 1;
            bool valid = (m0 + r) < M;
            const float* ap = A + (size_t)(m0 + r) * 256 + k0 + half * 32;
            int colb = half * 32;
#pragma unroll
            for (int i = 0; i < 8; i++) {
                float4 v = valid ? *(const float4*)(ap + i * 4)
                                 : make_float4(0.f, 0.f, 0.f, 0.f);
                __nv_bfloat16 h0 = __float2bfloat16(v.x);
                __nv_bfloat16 h1 = __float2bfloat16(v.y);
                __nv_bfloat16 h2 = __float2bfloat16(v.z);
                __nv_bfloat16 h3 = __float2bfloat16(v.w);
                __nv_bfloat16 l0 = __float2bfloat16(v.x - __bfloat162float(h0));
                __nv_bfloat16 l1 = __float2bfloat16(v.y - __bfloat162float(h1));
                __nv_bfloat16 l2 = __float2bfloat16(v.z - __bfloat162float(h2));
                __nv_bfloat16 l3 = __float2bfloat16(v.w - __bfloat162float(h3));
                int c = colb + i * 4;
                *(__nv_bfloat162*)(sAhi + (size_t)r * GST + c)     = __halves2bfloat162(h0, h1);
                *(__nv_bfloat162*)(sAhi + (size_t)r * GST + c + 2) = __halves2bfloat162(h2, h3);
                *(__nv_bfloat162*)(sAlo + (size_t)r * GST + c)     = __halves2bfloat162(l0, l1);
                *(__nv_bfloat162*)(sAlo + (size_t)r * GST + c + 2) = __halves2bfloat162(l2, l3);
            }
        }
        // stage B (already bf16 hi/lo, [Nc][256])
#pragma unroll
        for (int i = 0; i < 4; i++) {
            int c = tid * 4 + i;          // 0..1023 chunks of 8 bf16
            int n = c >> 3, ck = (c & 7) * 8;
            *(float4*)(sBhi + (size_t)n * GST + ck) =
                *(const float4*)(Whi + (size_t)(n0 + n) * 256 + k0 + ck);
            *(float4*)(sBlo + (size_t)n * GST + ck) =
                *(const float4*)(Wlo + (size_t)(n0 + n) * 256 + k0 + ck);
        }
        __syncthreads();

#pragma unroll
        for (int kk = 0; kk < 64; kk += 16) {
            unsigned ah[4][4], al[4][4], bh[4][2], bl[4][2];
#pragma unroll
            for (int mt = 0; mt < 4; mt++) {
                const __nv_bfloat16* p = sAhi + (size_t)(mbase + mt * 16 + g) * GST + kk + tq * 2;
                const __nv_bfloat16* q = sAlo + (size_t)(mbase + mt * 16 + g) * GST + kk + tq * 2;
                ah[mt][0] = *(const unsigned*)(p);
                ah[mt][1] = *(const unsigned*)(p + 8 * GST);
                ah[mt][2] = *(const unsigned*)(p + 8);
                ah[mt][3] = *(const unsigned*)(p + 8 * GST + 8);
                al[mt][0] = *(const unsigned*)(q);
                al[mt][1] = *(const unsigned*)(q + 8 * GST);
                al[mt][2] = *(const unsigned*)(q + 8);
                al[mt][3] = *(const unsigned*)(q + 8 * GST + 8);
            }
#pragma unroll
            for (int nt = 0; nt < 4; nt++) {
                const __nv_bfloat16* p = sBhi + (size_t)(nbase + nt * 8 + g) * GST + kk + tq * 2;
                const __nv_bfloat16* q = sBlo + (size_t)(nbase + nt * 8 + g) * GST + kk + tq * 2;
                bh[nt][0] = *(const unsigned*)(p);
                bh[nt][1] = *(const unsigned*)(p + 8);
                bl[nt][0] = *(const unsigned*)(q);
                bl[nt][1] = *(const unsigned*)(q + 8);
            }
#pragma unroll
            for (int mt = 0; mt < 4; mt++)
#pragma unroll
                for (int nt = 0; nt < 4; nt++) {
                    mma_bf16(acc[mt][nt], ah[mt], bh[nt]);
                    mma_bf16(acc[mt][nt], al[mt], bh[nt]);
                    mma_bf16(acc[mt][nt], ah[mt], bl[nt]);
                }
        }
        __syncthreads();
    }

    // epilogue
#pragma unroll
    for (int mt = 0; mt < 4; mt++) {
        int r0 = m0 + mbase + mt * 16 + g;
#pragma unroll
        for (int nt = 0; nt < 4; nt++) {
            int col = n0 + nbase + nt * 8 + tq * 2;
            float b0 = bias[col], b1 = bias[col + 1];
            if (r0 < M) {
                float v0 = acc[mt][nt][0] + b0;
                float v1 = acc[mt][nt][1] + b1;
                if (RELU) { v0 = fmaxf(v0, 0.f); v1 = fmaxf(v1, 0.f); }
                C[(size_t)r0 * Nc + col]     = v0;
                C[(size_t)r0 * Nc + col + 1] = v1;
            }
            if (r0 + 8 < M) {
                float v2 = acc[mt][nt][2] + b0;
                float v3 = acc[mt][nt][3] + b1;
                if (RELU) { v2 = fmaxf(v2, 0.f); v3 = fmaxf(v3, 0.f); }
                C[(size_t)(r0 + 8) * Nc + col]     = v2;
                C[(size_t)(r0 + 8) * Nc + col + 1] = v3;
            }
        }
    }
}

// ---------------- node attention, 4-row blocked ---------------------------
// smem: Ks[384][36], Vt[32][388], sp[32][388], sq[32][32]
#define KST 36
#define VST 388
__global__ void __launch_bounds__(256)
attn_kernel(const float* __restrict__ qkv,
            const float* __restrict__ kve,
            const unsigned char* __restrict__ nmask,
            float* __restrict__ out) {
    int h = blockIdx.x, b = blockIdx.y;
    extern __shared__ float smf[];
    float* Ks = smf;                      // 13824
    float* Vt = Ks + MT * KST;            // 12416
    float* sp = Vt + 32 * VST;            // 12416
    float* sq = sp + 32 * VST;            // 1024

    int tid = threadIdx.x;
    for (int idx = tid; idx < MT * 32; idx += 256) {
        int m = idx >> 5, d = idx & 31;
        float kv, vv;
        if (m < NN) {
            const float* base = qkv + (size_t)(b * NN + m) * 768 + h * 32 + d;
            kv = base[256]; vv = base[512];
        } else {
            const float* base = kve + (size_t)(b * EE + (m - NN)) * 512 + h * 32 + d;
            kv = base[0];   vv = base[256];
        }
        Ks[m * KST + d]  = kv;
        Vt[d * VST + m]  = vv;
    }
    __syncthreads();

    int w = tid >> 5, lane = tid & 31;
    const float scale = 0.17677669529663687f;

    for (int grp = 0; grp < 4; grp++) {
        int nrow0 = w * 4 + grp * 32;
        // load q rows into sq
#pragma unroll
        for (int i = 0; i < 4; i++)
            sq[(w * 4 + i) * 32 + lane] =
                qkv[(size_t)(b * NN + nrow0 + i) * 768 + h * 32 + lane];
        __syncwarp();

        const float4* q0 = (const float4*)(sq + (w * 4 + 0) * 32);
        const float4* q1 = (const float4*)(sq + (w * 4 + 1) * 32);
        const float4* q2 = (const float4*)(sq + (w * 4 + 2) * 32);
        const float4* q3 = (const float4*)(sq + (w * 4 + 3) * 32);
        const unsigned char* mr0 = nmask + (size_t)(b * NN + nrow0 + 0) * MT;
        const unsigned char* mr1 = nmask + (size_t)(b * NN + nrow0 + 1) * MT;
        const unsigned char* mr2 = nmask + (size_t)(b * NN + nrow0 + 2) * MT;
        const unsigned char* mr3 = nmask + (size_t)(b * NN + nrow0 + 3) * MT;
        float* p0 = sp + (w * 4 + 0) * VST;
        float* p1 = sp + (w * 4 + 1) * VST;
        float* p2 = sp + (w * 4 + 2) * VST;
        float* p3 = sp + (w * 4 + 3) * VST;

        float mx0 = -INFINITY, mx1 = -INFINITY, mx2 = -INFINITY, mx3 = -INFINITY;
#pragma unroll
        for (int j = 0; j < 12; j++) {
            int m = lane + j * 32;
            const float4* kr = (const float4*)(Ks + m * KST);
            float s0 = 0.f, s1 = 0.f, s2 = 0.f, s3 = 0.f;
#pragma unroll
            for (int dd = 0; dd < 8; dd++) {
                float4 kv = kr[dd];
                float4 a = q0[dd];
                s0 = fmaf(kv.x, a.x, fmaf(kv.y, a.y, fmaf(kv.z, a.z, fmaf(kv.w, a.w, s0))));
                a = q1[dd];
                s1 = fmaf(kv.x, a.x, fmaf(kv.y, a.y, fmaf(kv.z, a.z, fmaf(kv.w, a.w, s1))));
                a = q2[dd];
                s2 = fmaf(kv.x, a.x, fmaf(kv.y, a.y, fmaf(kv.z, a.z, fmaf(kv.w, a.w, s2))));
                a = q3[dd];
                s3 = fmaf(kv.x, a.x, fmaf(kv.y, a.y, fmaf(kv.z, a.z, fmaf(kv.w, a.w, s3))));
            }
            s0 *= scale; s1 *= scale; s2 *= scale; s3 *= scale;
            if (mr0[m]) s0 = -INFINITY;
            if (mr1[m]) s1 = -INFINITY;
            if (mr2[m]) s2 = -INFINITY;
            if (mr3[m]) s3 = -INFINITY;
            p0[m] = s0; p1[m] = s1; p2[m] = s2; p3[m] = s3;
            mx0 = fmaxf(mx0, s0); mx1 = fmaxf(mx1, s1);
            mx2 = fmaxf(mx2, s2); mx3 = fmaxf(mx3, s3);
        }
#pragma unroll
        for (int o = 16; o; o >>= 1) {
            mx0 = fmaxf(mx0, __shfl_xor_sync(0xffffffffu, mx0, o));
            mx1 = fmaxf(mx1, __shfl_xor_sync(0xffffffffu, mx1, o));
            mx2 = fmaxf(mx2, __shfl_xor_sync(0xffffffffu, mx2, o));
            mx3 = fmaxf(mx3, __shfl_xor_sync(0xffffffffu, mx3, o));
        }
        float su0 = 0.f, su1 = 0.f, su2 = 0.f, su3 = 0.f;
#pragma unroll
        for (int j = 0; j < 12; j++) {
            int m = lane + j * 32;
            float e0 = __expf(p0[m] - mx0); p0[m] = e0; su0 += e0;
            float e1 = __expf(p1[m] - mx1); p1[m] = e1; su1 += e1;
            float e2 = __expf(p2[m] - mx2); p2[m] = e2; su2 += e2;
            float e3 = __expf(p3[m] - mx3); p3[m] = e3; su3 += e3;
        }
#pragma unroll
        for (int o = 16; o; o >>= 1) {
            su0 += __shfl_xor_sync(0xffffffffu, su0, o);
            su1 += __shfl_xor_sync(0xffffffffu, su1, o);
            su2 += __shfl_xor_sync(0xffffffffu, su2, o);
            su3 += __shfl_xor_sync(0xffffffffu, su3, o);
        }
        __syncwarp();

        const float4* vt4 = (const float4*)(Vt + lane * VST);
        const float4* pp0 = (const float4*)p0;
        const float4* pp1 = (const float4*)p1;
        const float4* pp2 = (const float4*)p2;
        const float4* pp3 = (const float4*)p3;
        float o0 = 0.f, o1 = 0.f, o2 = 0.f, o3 = 0.f;
#pragma unroll 8
        for (int mc = 0; mc < MT / 4; mc++) {
            float4 v = vt4[mc];
            float4 a = pp0[mc];
            o0 = fmaf(v.x, a.x, fmaf(v.y, a.y, fmaf(v.z, a.z, fmaf(v.w, a.w, o0))));
            a = pp1[mc];
            o1 = fmaf(v.x, a.x, fmaf(v.y, a.y, fmaf(v.z, a.z, fmaf(v.w, a.w, o1))));
            a = pp2[mc];
            o2 = fmaf(v.x, a.x, fmaf(v.y, a.y, fmaf(v.z, a.z, fmaf(v.w, a.w, o2))));
            a = pp3[mc];
            o3 = fmaf(v.x, a.x, fmaf(v.y, a.y, fmaf(v.z, a.z, fmaf(v.w, a.w, o3))));
        }
        size_t ob = (size_t)(b * NN + nrow0) * DD + h * 32 + lane;
        out[ob]          = o0 / su0;
        out[ob + DD]     = o1 / su1;
        out[ob + 2 * DD] = o2 / su2;
        out[ob + 3 * DD] = o3 / su3;
        __syncwarp();
    }
}

// ---------------- LayerNorm over last dim (256) ---------------------------
__global__ void ln_kernel(const float* __restrict__ A,
                          const float* __restrict__ Badd,
                          const float* __restrict__ g,
                          const float* __restrict__ be,
                          float* __restrict__ out) {
    __shared__ float scratch[8];
    int row = blockIdx.x, t = threadIdx.x;
    size_t base = (size_t)row * DD;
    float v = A[base + t] + Badd[base + t];

    float s = v;
#pragma unroll
    for (int o = 16; o; o >>= 1) s += __shfl_xor_sync(0xffffffffu, s, o);
    if ((t & 31) == 0) scratch[t >> 5] = s;
    __syncthreads();
    float tot = 0.f;
#pragma unroll
    for (int i = 0; i < 8; i++) tot += scratch[i];
    float mean = tot * (1.f / 256.f);
    float d = v - mean;
    __syncthreads();

    s = d * d;
#pragma unroll
    for (int o = 16; o; o >>= 1) s += __shfl_xor_sync(0xffffffffu, s, o);
    if ((t & 31) == 0) scratch[t >> 5] = s;
    __syncthreads();
    float tot2 = 0.f;
#pragma unroll
    for (int i = 0; i < 8; i++) tot2 += scratch[i];
    float var = tot2 * (1.f / 256.f);

    out[base + t] = d * rsqrtf(var + 1e-5f) * g[t] + be[t];
}

// ---------------- assemble tok = [CLS; x] --------------------------------
__global__ void tok_kernel(const float* __restrict__ CLS,
                           const float* __restrict__ x,
                           float* __restrict__ tok) {
    int r = blockIdx.x;
    int b = r / NT, t = r % NT;
    int c = threadIdx.x;
    tok[(size_t)r * DD + c] = (t == 0)
        ? CLS[(size_t)b * DD + c]
        : x[(size_t)(b * NN + (t - 1)) * DD + c];
}

// ---------------- CLS attention -------------------------------------------
__global__ void cls_attn_kernel(const float* __restrict__ CLS,
                                const float* __restrict__ rkv,
                                const unsigned char* __restrict__ cmask,
                                float* __restrict__ cls2) {
    int b = blockIdx.x;
    __shared__ float sq[8 * 32];
    __shared__ float sp[8 * 160];
    int tid = threadIdx.x, h = tid >> 5, lane = tid & 31;

    sq[h * 32 + lane] = CLS[(size_t)b * DD + h * 32 + lane];
    __syncwarp();
    const float scale = 0.17677669529663687f;
    const float* sqh = sq + h * 32;

    float svals[5];
    float smax = -INFINITY;
#pragma unroll
    for (int j = 0; j < 5; j++) {
        int m = lane + j * 32;
        float s = -INFINITY;
        if (m < NT) {
            const float* kr = rkv + (size_t)(b * NT + m) * 512 + h * 32;
            float s0 = 0.f;
#pragma unroll
            for (int d = 0; d < 32; d++) s0 = fmaf(sqh[d], kr[d], s0);
            s = s0 * scale;
            if (cmask[(size_t)b * NT + m]) s = -INFINITY;
        }
        svals[j] = s;
        smax = fmaxf(smax, s);
    }
#pragma unroll
    for (int o = 16; o; o >>= 1)
        smax = fmaxf(smax, __shfl_xor_sync(0xffffffffu, smax, o));

    float ssum = 0.f;
#pragma unroll
    for (int j = 0; j < 5; j++) {
        float p = __expf(svals[j] - smax);
        ssum += p;
        sp[h * 160 + lane + j * 32] = p;
    }
#pragma unroll
    for (int o = 16; o; o >>= 1)
        ssum += __shfl_xor_sync(0xffffffffu, ssum, o);
    __syncwarp();

    float inv = 1.f / ssum;
    float acc = 0.f;
    for (int m = 0; m < NT; m++)
        acc = fmaf(sp[h * 160 + m],
                   rkv[(size_t)(b * NT + m) * 512 + 256 + h * 32 + lane], acc);
    cls2[(size_t)b * DD + h * 32 + lane] = acc * inv;
}

// ---------------- launch --------------------------------------------------
extern "C" void kernel_launch(void* const* d_in, const int* in_sizes, int n_in,
                              void* d_out, int out_size) {
    const float* node_x   = (const float*)d_in[0];
    const float* edge_x   = (const float*)d_in[1];
    const float* CLS      = (const float*)d_in[2];
    const unsigned char* nmask = (const unsigned char*)d_in[3];
    const unsigned char* cmask = (const unsigned char*)d_in[4];
    const float* w_qkv    = (const float*)d_in[5];
    const float* b_qkv    = (const float*)d_in[6];
    const float* w_kve    = (const float*)d_in[7];
    const float* b_kve    = (const float*)d_in[8];
    const float* w1       = (const float*)d_in[9];
    const float* b1       = (const float*)d_in[10];
    const float* w2       = (const float*)d_in[11];
    const float* b2       = (const float*)d_in[12];
    const float* g1       = (const float*)d_in[13];
    const float* be1      = (const float*)d_in[14];
    const float* g2       = (const float*)d_in[15];
    const float* be2      = (const float*)d_in[16];
    const float* ro_w_kv  = (const float*)d_in[17];
    const float* ro_b_kv  = (const float*)d_in[18];
    const float* ro_w1    = (const float*)d_in[19];
    const float* ro_b1    = (const float*)d_in[20];
    const float* ro_w2    = (const float*)d_in[21];
    const float* ro_b2    = (const float*)d_in[22];
    const float* ro_g1    = (const float*)d_in[23];
    const float* ro_be1   = (const float*)d_in[24];
    const float* ro_g2    = (const float*)d_in[25];
    const float* ro_be2   = (const float*)d_in[26];

    float* out_x = (float*)d_out;
    float* out_c = out_x + (size_t)BB * NN * DD;

    float *p_qkv, *p_kve, *p_attn, *p_x1, *p_h1, *p_ff, *p_tok, *p_rkv;
    float *p_cls2, *p_c1, *p_ch1, *p_cff;
    __nv_bfloat16 *whi, *wlo;
    cudaGetSymbolAddress((void**)&p_qkv,  g_qkv);
    cudaGetSymbolAddress((void**)&p_kve,  g_kve);
    cudaGetSymbolAddress((void**)&p_attn, g_attn);
    cudaGetSymbolAddress((void**)&p_x1,   g_x1);
    cudaGetSymbolAddress((void**)&p_h1,   g_h1);
    cudaGetSymbolAddress((void**)&p_ff,   g_ff);
    cudaGetSymbolAddress((void**)&p_tok,  g_tok);
    cudaGetSymbolAddress((void**)&p_rkv,  g_rkv);
    cudaGetSymbolAddress((void**)&p_cls2, g_cls2);
    cudaGetSymbolAddress((void**)&p_c1,   g_c1);
    cudaGetSymbolAddress((void**)&p_ch1,  g_ch1);
    cudaGetSymbolAddress((void**)&p_cff,  g_cff);
    cudaGetSymbolAddress((void**)&whi,    g_whi);
    cudaGetSymbolAddress((void**)&wlo,    g_wlo);

    const int gemm_smem = 4 * 128 * GST * (int)sizeof(__nv_bfloat16);  // 73728
    cudaFuncSetAttribute(gemm_mma<false>, cudaFuncAttributeMaxDynamicSharedMemorySize, gemm_smem);
    cudaFuncSetAttribute(gemm_mma<true>,  cudaFuncAttributeMaxDynamicSharedMemorySize, gemm_smem);
    const int attn_smem = (MT * KST + 32 * VST + 32 * VST + 32 * 32) * (int)sizeof(float);
    cudaFuncSetAttribute(attn_kernel, cudaFuncAttributeMaxDynamicSharedMemorySize, attn_smem);

    // weight conversions
    conv_w<false><<<768, 256>>>(w_qkv,    whi + OFF_QKV,  wlo + OFF_QKV,  768);
    conv_w<false><<<512, 256>>>(w_kve,    whi + OFF_KVE,  wlo + OFF_KVE,  512);
    conv_w<true ><<<256, 256>>>(w1,       whi + OFF_W1,   wlo + OFF_W1,   256);
    conv_w<true ><<<256, 256>>>(w2,       whi + OFF_W2,   wlo + OFF_W2,   256);
    conv_w<false><<<512, 256>>>(ro_w_kv,  whi + OFF_ROKV, wlo + OFF_ROKV, 512);
    conv_w<true ><<<256, 256>>>(ro_w1,    whi + OFF_ROW1, wlo + OFF_ROW1, 256);
    conv_w<true ><<<256, 256>>>(ro_w2,    whi + OFF_ROW2, wlo + OFF_ROW2, 256);

    // projections
    gemm_mma<false><<<dim3(6, 64),  256, gemm_smem>>>(node_x, whi + OFF_QKV, wlo + OFF_QKV, b_qkv, p_qkv, BB * NN, 768);
    gemm_mma<false><<<dim3(4, 128), 256, gemm_smem>>>(edge_x, whi + OFF_KVE, wlo + OFF_KVE, b_kve, p_kve, BB * EE, 512);

    attn_kernel<<<dim3(HH, BB), 256, attn_smem>>>(p_qkv, p_kve, nmask, p_attn);

    ln_kernel<<<BB * NN, 256>>>(node_x, p_attn, g1, be1, p_x1);
    gemm_mma<true ><<<dim3(2, 64), 256, gemm_smem>>>(p_x1, whi + OFF_W1, wlo + OFF_W1, b1, p_h1, BB * NN, 256);
    gemm_mma<false><<<dim3(2, 64), 256, gemm_smem>>>(p_h1, whi + OFF_W2, wlo + OFF_W2, b2, p_ff, BB * NN, 256);
    ln_kernel<<<BB * NN, 256>>>(p_x1, p_ff, g2, be2, out_x);

    // readout
    tok_kernel<<<BB * NT, 256>>>(CLS, out_x, p_tok);
    gemm_mma<false><<<dim3(4, 65), 256, gemm_smem>>>(p_tok, whi + OFF_ROKV, wlo + OFF_ROKV, ro_b_kv, p_rkv, BB * NT, 512);
    cls_attn_kernel<<<BB, 256>>>(CLS, p_rkv, cmask, p_cls2);
    ln_kernel<<<BB, 256>>>(CLS, p_cls2, ro_g1, ro_be1, p_c1);
    gemm_mma<true ><<<dim3(2, 1), 256, gemm_smem>>>(p_c1,  whi + OFF_ROW1, wlo + OFF_ROW1, ro_b1, p_ch1, BB, 256);
    gemm_mma<false><<<dim3(2, 1), 256, gemm_smem>>>(p_ch1, whi + OFF_ROW2, wlo + OFF_ROW2, ro_b2, p_cff, BB, 256);
    ln_kernel<<<BB, 256>>>(p_c1, p_cff, ro_g2, ro_be2, out_c);
}

// round 5
// speedup vs baseline: 1.5636x; 1.0890x over previous
#include <cuda_runtime.h>
#include <cuda_bf16.h>
#include <math.h>

// Shapes
#define BB   64
#define NN   128
#define EE   256
#define DD   256
#define HH   8
#define MT   384   // N + E
#define NT   129   // N + 1

// ---------------- scratch (device globals; no allocation) ----------------
__device__ float g_qkv [BB*NN*3*DD];
__device__ float g_kve [BB*EE*2*DD];
__device__ float g_attn[BB*NN*DD];
__device__ float g_x1  [BB*NN*DD];
__device__ float g_h1  [BB*NN*DD];
__device__ float g_ff  [BB*NN*DD];
__device__ float g_tok [BB*NT*DD];
__device__ float g_rkv [BB*NT*2*DD];
__device__ float g_cls2[BB*DD];
__device__ float g_c1  [BB*DD];
__device__ float g_ch1 [BB*DD];
__device__ float g_cff [BB*DD];

// bf16 hi/lo weight buffers, layout [Nc][256] (k contiguous)
#define OFF_QKV   0
#define OFF_KVE   (OFF_QKV + 768*256)
#define OFF_W1    (OFF_KVE + 512*256)
#define OFF_W2    (OFF_W1  + 256*256)
#define OFF_ROKV  (OFF_W2  + 256*256)
#define OFF_ROW1  (OFF_ROKV+ 512*256)
#define OFF_ROW2  (OFF_ROW1+ 256*256)
#define W_TOTAL   (OFF_ROW2+ 256*256)
__device__ __nv_bfloat16 g_whi[W_TOTAL];
__device__ __nv_bfloat16 g_wlo[W_TOTAL];

// ---------------- fused weight conversion (one launch) -------------------
__global__ void conv_all(const float* __restrict__ w_qkv,
                         const float* __restrict__ w_kve,
                         const float* __restrict__ w1,
                         const float* __restrict__ w2,
                         const float* __restrict__ ro_w_kv,
                         const float* __restrict__ ro_w1,
                         const float* __restrict__ ro_w2,
                         __nv_bfloat16* __restrict__ hi,
                         __nv_bfloat16* __restrict__ lo) {
    int i = blockIdx.x * 256 + threadIdx.x;
    if (i >= W_TOTAL) return;
    const float* W; int Nc; bool direct; int off;
    if      (i < OFF_KVE ) { W = w_qkv;   Nc = 768; direct = false; off = OFF_QKV;  }
    else if (i < OFF_W1  ) { W = w_kve;   Nc = 512; direct = false; off = OFF_KVE;  }
    else if (i < OFF_W2  ) { W = w1;      Nc = 256; direct = true;  off = OFF_W1;   }
    else if (i < OFF_ROKV) { W = w2;      Nc = 256; direct = true;  off = OFF_W2;   }
    else if (i < OFF_ROW1) { W = ro_w_kv; Nc = 512; direct = false; off = OFF_ROKV; }
    else if (i < OFF_ROW2) { W = ro_w1;   Nc = 256; direct = true;  off = OFF_ROW1; }
    else                   { W = ro_w2;   Nc = 256; direct = true;  off = OFF_ROW2; }
    int li = i - off;
    int n = li >> 8, k = li & 255;
    float v = direct ? W[(size_t)n * 256 + k] : W[(size_t)k * Nc + n];
    __nv_bfloat16 h = __float2bfloat16(v);
    hi[i] = h;
    lo[i] = __float2bfloat16(v - __bfloat162float(h));
}

// ---------------- bf16-split tensor-core GEMM ----------------------------
__device__ __forceinline__ void mma_bf16(float* c, const unsigned* a, const unsigned* b) {
    asm volatile(
        "mma.sync.aligned.m16n8k16.row.col.f32.bf16.bf16.f32 "
        "{%0,%1,%2,%3}, {%4,%5,%6,%7}, {%8,%9}, {%0,%1,%2,%3};\n"
        : "+f"(c[0]), "+f"(c[1]), "+f"(c[2]), "+f"(c[3])
        : "r"(a[0]), "r"(a[1]), "r"(a[2]), "r"(a[3]), "r"(b[0]), "r"(b[1]));
}

#define GST 72   // smem row stride in bf16 (64 data + 8 pad)

template<bool RELU>
__global__ void __launch_bounds__(256)
gemm_mma(const float* __restrict__ A,
         const __nv_bfloat16* __restrict__ Whi,
         const __nv_bfloat16* __restrict__ Wlo,
         const float* __restrict__ bias,
         float* __restrict__ C, int M, int Nc) {
    extern __shared__ __nv_bfloat16 sm[];
    __nv_bfloat16* sAhi = sm;
    __nv_bfloat16* sAlo = sAhi + 128 * GST;
    __nv_bfloat16* sBhi = sAlo + 128 * GST;
    __nv_bfloat16* sBlo = sBhi + 128 * GST;

    int tid = threadIdx.x;
    int lane = tid & 31, warp = tid >> 5;
    int g = lane >> 2, tq = lane & 3;
    int mbase = (warp >> 2) * 64;
    int nbase = (warp & 3) * 32;
    int m0 = blockIdx.y * 128;
    int n0 = blockIdx.x * 128;

    float acc[4][4][4];
#pragma unroll
    for (int mt = 0; mt < 4; mt++)
#pragma unroll
        for (int nt = 0; nt < 4; nt++)
#pragma unroll
            for (int i = 0; i < 4; i++) acc[mt][nt][i] = 0.f;

    for (int k0 = 0; k0 < 256; k0 += 64) {
        {
            int r = tid >> 1, half = tid & 1;
            bool valid = (m0 + r) < M;
            const float* ap = A + (size_t)(m0 + r) * 256 + k0 + half * 32;
            int colb = half * 32;
#pragma unroll
            for (int i = 0; i < 8; i++) {
                float4 v = valid ? *(const float4*)(ap + i * 4)
                                 : make_float4(0.f, 0.f, 0.f, 0.f);
                __nv_bfloat16 h0 = __float2bfloat16(v.x);
                __nv_bfloat16 h1 = __float2bfloat16(v.y);
                __nv_bfloat16 h2 = __float2bfloat16(v.z);
                __nv_bfloat16 h3 = __float2bfloat16(v.w);
                __nv_bfloat16 l0 = __float2bfloat16(v.x - __bfloat162float(h0));
                __nv_bfloat16 l1 = __float2bfloat16(v.y - __bfloat162float(h1));
                __nv_bfloat16 l2 = __float2bfloat16(v.z - __bfloat162float(h2));
                __nv_bfloat16 l3 = __float2bfloat16(v.w - __bfloat162float(h3));
                int c = colb + i * 4;
                *(__nv_bfloat162*)(sAhi + (size_t)r * GST + c)     = __halves2bfloat162(h0, h1);
                *(__nv_bfloat162*)(sAhi + (size_t)r * GST + c + 2) = __halves2bfloat162(h2, h3);
                *(__nv_bfloat162*)(sAlo + (size_t)r * GST + c)     = __halves2bfloat162(l0, l1);
                *(__nv_bfloat162*)(sAlo + (size_t)r * GST + c + 2) = __halves2bfloat162(l2, l3);
            }
        }
#pragma unroll
        for (int i = 0; i < 4; i++) {
            int c = tid * 4 + i;
            int n = c >> 3, ck = (c & 7) * 8;
            *(float4*)(sBhi + (size_t)n * GST + ck) =
                *(const float4*)(Whi + (size_t)(n0 + n) * 256 + k0 + ck);
            *(float4*)(sBlo + (size_t)n * GST + ck) =
                *(const float4*)(Wlo + (size_t)(n0 + n) * 256 + k0 + ck);
        }
        __syncthreads();

#pragma unroll
        for (int kk = 0; kk < 64; kk += 16) {
            unsigned ah[4][4], al[4][4], bh[4][2], bl[4][2];
#pragma unroll
            for (int mt = 0; mt < 4; mt++) {
                const __nv_bfloat16* p = sAhi + (size_t)(mbase + mt * 16 + g) * GST + kk + tq * 2;
                const __nv_bfloat16* q = sAlo + (size_t)(mbase + mt * 16 + g) * GST + kk + tq * 2;
                ah[mt][0] = *(const unsigned*)(p);
                ah[mt][1] = *(const unsigned*)(p + 8 * GST);
                ah[mt][2] = *(const unsigned*)(p + 8);
                ah[mt][3] = *(const unsigned*)(p + 8 * GST + 8);
                al[mt][0] = *(const unsigned*)(q);
                al[mt][1] = *(const unsigned*)(q + 8 * GST);
                al[mt][2] = *(const unsigned*)(q + 8);
                al[mt][3] = *(const unsigned*)(q + 8 * GST + 8);
            }
#pragma unroll
            for (int nt = 0; nt < 4; nt++) {
                const __nv_bfloat16* p = sBhi + (size_t)(nbase + nt * 8 + g) * GST + kk + tq * 2;
                const __nv_bfloat16* q = sBlo + (size_t)(nbase + nt * 8 + g) * GST + kk + tq * 2;
                bh[nt][0] = *(const unsigned*)(p);
                bh[nt][1] = *(const unsigned*)(p + 8);
                bl[nt][0] = *(const unsigned*)(q);
                bl[nt][1] = *(const unsigned*)(q + 8);
            }
#pragma unroll
            for (int mt = 0; mt < 4; mt++)
#pragma unroll
                for (int nt = 0; nt < 4; nt++) {
                    mma_bf16(acc[mt][nt], ah[mt], bh[nt]);
                    mma_bf16(acc[mt][nt], al[mt], bh[nt]);
                    mma_bf16(acc[mt][nt], ah[mt], bl[nt]);
                }
        }
        __syncthreads();
    }

#pragma unroll
    for (int mt = 0; mt < 4; mt++) {
        int r0 = m0 + mbase + mt * 16 + g;
#pragma unroll
        for (int nt = 0; nt < 4; nt++) {
            int col = n0 + nbase + nt * 8 + tq * 2;
            float b0 = bias[col], b1 = bias[col + 1];
            if (r0 < M) {
                float v0 = acc[mt][nt][0] + b0;
                float v1 = acc[mt][nt][1] + b1;
                if (RELU) { v0 = fmaxf(v0, 0.f); v1 = fmaxf(v1, 0.f); }
                C[(size_t)r0 * Nc + col]     = v0;
                C[(size_t)r0 * Nc + col + 1] = v1;
            }
            if (r0 + 8 < M) {
                float v2 = acc[mt][nt][2] + b0;
                float v3 = acc[mt][nt][3] + b1;
                if (RELU) { v2 = fmaxf(v2, 0.f); v3 = fmaxf(v3, 0.f); }
                C[(size_t)(r0 + 8) * Nc + col]     = v2;
                C[(size_t)(r0 + 8) * Nc + col + 1] = v3;
            }
        }
    }
}

// ---------------- node attention on tensor cores --------------------------
// Block = 64 q-rows of one (b,h). grid (16=h*2+rb, 64=b)
// smem strides chosen so (stride_in_4B mod 32) in {4,12,20,28} -> conflict-free
#define ATT_SSTR 388   // S row stride in floats (388 mod 32 = 4 in 4B units)
#define ATT_PSTR 776   // = 2*ATT_SSTR, P row stride in bf16
#define ATT_KSTR 40    // Q/K row stride in bf16 (20 in 4B units)
#define ATT_VSTR 392   // Vt row stride in bf16 (196 mod 32 = 4)
#define ATT_SMEM (64*ATT_SSTR*4 + (2*384*ATT_KSTR + 2*32*ATT_VSTR + 2*64*ATT_KSTR)*2 + 64*4)

__global__ void __launch_bounds__(256)
attn_mma(const float* __restrict__ qkv,
         const float* __restrict__ kve,
         const unsigned char* __restrict__ nmask,
         float* __restrict__ out) {
    int h = blockIdx.x >> 1, rb = blockIdx.x & 1, b = blockIdx.y;
    int m0b = rb * 64;
    extern __shared__ float smf[];
    float* S = smf;                                              // 64 x 388 fp32
    __nv_bfloat16* Khi  = (__nv_bfloat16*)(S + 64 * ATT_SSTR);   // 384 x 40
    __nv_bfloat16* Klo  = Khi  + 384 * ATT_KSTR;
    __nv_bfloat16* Vthi = Klo  + 384 * ATT_KSTR;                 // 32 x 392 (transposed)
    __nv_bfloat16* Vtlo = Vthi + 32 * ATT_VSTR;
    __nv_bfloat16* Qhi  = Vtlo + 32 * ATT_VSTR;                  // 64 x 40
    __nv_bfloat16* Qlo  = Qhi  + 64 * ATT_KSTR;
    float* stats = (float*)(Qlo + 64 * ATT_KSTR);                // 64 inv-sums

    int tid = threadIdx.x;
    // stage K (hi/lo) and V^T (hi/lo)
    for (int idx = tid; idx < MT * 32; idx += 256) {
        int m = idx >> 5, d = idx & 31;
        float kv, vv;
        if (m < NN) {
            const float* base = qkv + (size_t)(b * NN + m) * 768 + h * 32 + d;
            kv = base[256]; vv = base[512];
        } else {
            const float* base = kve + (size_t)(b * EE + (m - NN)) * 512 + h * 32 + d;
            kv = base[0];   vv = base[256];
        }
        __nv_bfloat16 kh = __float2bfloat16(kv);
        Khi[m * ATT_KSTR + d] = kh;
        Klo[m * ATT_KSTR + d] = __float2bfloat16(kv - __bfloat162float(kh));
        __nv_bfloat16 vh = __float2bfloat16(vv);
        Vthi[d * ATT_VSTR + m] = vh;
        Vtlo[d * ATT_VSTR + m] = __float2bfloat16(vv - __bfloat162float(vh));
    }
    // stage Q rows (hi/lo)
    for (int idx = tid; idx < 64 * 32; idx += 256) {
        int r = idx >> 5, d = idx & 31;
        float qv = qkv[(size_t)(b * NN + m0b + r) * 768 + h * 32 + d];
        __nv_bfloat16 qh = __float2bfloat16(qv);
        Qhi[r * ATT_KSTR + d] = qh;
        Qlo[r * ATT_KSTR + d] = __float2bfloat16(qv - __bfloat162float(qh));
    }
    __syncthreads();

    int lane = tid & 31, warp = tid >> 5;
    int g = lane >> 2, tq = lane & 3;

    // ===== phase 1: S = Q @ K^T (hi/lo, 3 passes) =====
    {
        int wm = warp >> 2;      // 0..1 -> m-tiles {2wm, 2wm+1}
        int wn = warp & 3;       // 0..3 -> n-tiles wn*12 .. +11
        float acc[2][12][4];
#pragma unroll
        for (int mt = 0; mt < 2; mt++)
#pragma unroll
            for (int nt = 0; nt < 12; nt++)
#pragma unroll
                for (int i = 0; i < 4; i++) acc[mt][nt][i] = 0.f;

#pragma unroll
        for (int kk = 0; kk < 32; kk += 16) {
            unsigned ah[2][4], al[2][4];
#pragma unroll
            for (int mt = 0; mt < 2; mt++) {
                int row = (wm * 2 + mt) * 16 + g;
                const __nv_bfloat16* p = Qhi + row * ATT_KSTR + kk + tq * 2;
                const __nv_bfloat16* q = Qlo + row * ATT_KSTR + kk + tq * 2;
                ah[mt][0] = *(const unsigned*)(p);
                ah[mt][1] = *(const unsigned*)(p + 8 * ATT_KSTR);
                ah[mt][2] = *(const unsigned*)(p + 8);
                ah[mt][3] = *(const unsigned*)(p + 8 * ATT_KSTR + 8);
                al[mt][0] = *(const unsigned*)(q);
                al[mt][1] = *(const unsigned*)(q + 8 * ATT_KSTR);
                al[mt][2] = *(const unsigned*)(q + 8);
                al[mt][3] = *(const unsigned*)(q + 8 * ATT_KSTR + 8);
            }
#pragma unroll
            for (int nt = 0; nt < 12; nt++) {
                int ncol = (wn * 12 + nt) * 8 + g;
                const __nv_bfloat16* pb = Khi + ncol * ATT_KSTR + kk + tq * 2;
                const __nv_bfloat16* ql = Klo + ncol * ATT_KSTR + kk + tq * 2;
                unsigned bh[2] = { *(const unsigned*)(pb), *(const unsigned*)(pb + 8) };
                unsigned bl[2] = { *(const unsigned*)(ql), *(const unsigned*)(ql + 8) };
#pragma unroll
                for (int mt = 0; mt < 2; mt++) {
                    mma_bf16(acc[mt][nt], ah[mt], bh);
                    mma_bf16(acc[mt][nt], al[mt], bh);
                    mma_bf16(acc[mt][nt], ah[mt], bl);
                }
            }
        }
        // write S
#pragma unroll
        for (int mt = 0; mt < 2; mt++) {
            int row = (wm * 2 + mt) * 16 + g;
#pragma unroll
            for (int nt = 0; nt < 12; nt++) {
                int col = (wn * 12 + nt) * 8 + tq * 2;
                *(float2*)(S + (size_t)row * ATT_SSTR + col) =
                    make_float2(acc[mt][nt][0], acc[mt][nt][1]);
                *(float2*)(S + (size_t)(row + 8) * ATT_SSTR + col) =
                    make_float2(acc[mt][nt][2], acc[mt][nt][3]);
            }
        }
    }
    __syncthreads();

    // ===== phase 2: softmax (fp32) + in-place P hi/lo (bf16) =====
    const float scale = 0.17677669529663687f;
#pragma unroll
    for (int r8 = 0; r8 < 8; r8++) {
        int row = warp * 8 + r8;
        float* srow = S + (size_t)row * ATT_SSTR;
        const unsigned char* mrow = nmask + (size_t)(b * NN + m0b + row) * MT;
        float sv[12];
        float mx = -INFINITY;
#pragma unroll
        for (int j = 0; j < 12; j++) {
            int m = lane + j * 32;
            float s = srow[m] * scale;
            if (mrow[m]) s = -INFINITY;
            sv[j] = s;
            mx = fmaxf(mx, s);
        }
#pragma unroll
        for (int o = 16; o; o >>= 1)
            mx = fmaxf(mx, __shfl_xor_sync(0xffffffffu, mx, o));
        float su = 0.f;
        float pv[12];
#pragma unroll
        for (int j = 0; j < 12; j++) {
            pv[j] = __expf(sv[j] - mx);
            su += pv[j];
        }
#pragma unroll
        for (int o = 16; o; o >>= 1)
            su += __shfl_xor_sync(0xffffffffu, su, o);
        __syncwarp();
        __nv_bfloat16* prow = (__nv_bfloat16*)srow;   // bf16 view, row = 776 bf16
#pragma unroll
        for (int j = 0; j < 12; j++) {
            int m = lane + j * 32;
            __nv_bfloat16 ph = __float2bfloat16(pv[j]);
            prow[m]       = ph;                                             // Phi
            prow[388 + m] = __float2bfloat16(pv[j] - __bfloat162float(ph)); // Plo
        }
        if (lane == 0) stats[row] = 1.f / su;
    }
    __syncthreads();

    // ===== phase 3: O = P @ V (hi/lo, 3 passes) =====
    {
        int wm = warp >> 1;            // m-tile 0..3
        int wn2 = (warp & 1) * 2;      // n-tiles {wn2, wn2+1}
        float acc[2][4];
#pragma unroll
        for (int nt = 0; nt < 2; nt++)
#pragma unroll
            for (int i = 0; i < 4; i++) acc[nt][i] = 0.f;

        int row = wm * 16 + g;
        const __nv_bfloat16* prow = (const __nv_bfloat16*)S;
#pragma unroll 4
        for (int kk = 0; kk < MT; kk += 16) {
            const __nv_bfloat16* pr = prow + (size_t)row * ATT_PSTR + kk + tq * 2;
            unsigned ah[4], al[4];
            ah[0] = *(const unsigned*)(pr);
            ah[1] = *(const unsigned*)(pr + 8 * ATT_PSTR);
            ah[2] = *(const unsigned*)(pr + 8);
            ah[3] = *(const unsigned*)(pr + 8 * ATT_PSTR + 8);
            al[0] = *(const unsigned*)(pr + 388);
            al[1] = *(const unsigned*)(pr + 8 * ATT_PSTR + 388);
            al[2] = *(const unsigned*)(pr + 388 + 8);
            al[3] = *(const unsigned*)(pr + 8 * ATT_PSTR + 388 + 8);
#pragma unroll
            for (int nt = 0; nt < 2; nt++) {
                int dim = (wn2 + nt) * 8 + g;
                const __nv_bfloat16* pv_ = Vthi + (size_t)dim * ATT_VSTR + kk + tq * 2;
                const __nv_bfloat16* pw  = Vtlo + (size_t)dim * ATT_VSTR + kk + tq * 2;
                unsigned bh[2] = { *(const unsigned*)(pv_), *(const unsigned*)(pv_ + 8) };
                unsigned bl[2] = { *(const unsigned*)(pw),  *(const unsigned*)(pw + 8)  };
                mma_bf16(acc[nt], ah, bh);
                mma_bf16(acc[nt], al, bh);
                mma_bf16(acc[nt], ah, bl);
            }
        }
        float inv0 = stats[row], inv1 = stats[row + 8];
#pragma unroll
        for (int nt = 0; nt < 2; nt++) {
            int col = (wn2 + nt) * 8 + tq * 2;
            size_t ob = (size_t)(b * NN + m0b + row) * DD + h * 32 + col;
            out[ob]              = acc[nt][0] * inv0;
            out[ob + 1]          = acc[nt][1] * inv0;
            out[ob + 8 * DD]     = acc[nt][2] * inv1;
            out[ob + 8 * DD + 1] = acc[nt][3] * inv1;
        }
    }
}

// ---------------- LayerNorm, 4 rows per block, float4 ---------------------
__global__ void __launch_bounds__(256)
ln4(const float* __restrict__ A, const float* __restrict__ Badd,
    const float* __restrict__ g, const float* __restrict__ be,
    float* __restrict__ out, int nrows) {
    __shared__ float part[16];
    int sub = threadIdx.x >> 6;        // row within block
    int t   = threadIdx.x & 63;
    int w   = threadIdx.x >> 5;
    int row = blockIdx.x * 4 + sub;
    bool valid = row < nrows;
    size_t base = (size_t)row * DD + t * 4;
    float4 a = make_float4(0.f, 0.f, 0.f, 0.f);
    if (valid) {
        a = *(const float4*)(A + base);
        float4 bb = *(const float4*)(Badd + base);
        a.x += bb.x; a.y += bb.y; a.z += bb.z; a.w += bb.w;
    }
    float s = a.x + a.y + a.z + a.w;
#pragma unroll
    for (int o = 16; o; o >>= 1) s += __shfl_xor_sync(0xffffffffu, s, o);
    if ((threadIdx.x & 31) == 0) part[w] = s;
    __syncthreads();
    float mean = (part[sub * 2] + part[sub * 2 + 1]) * (1.f / 256.f);
    float dx = a.x - mean, dy = a.y - mean, dz = a.z - mean, dw = a.w - mean;
    float q = dx * dx + dy * dy + dz * dz + dw * dw;
#pragma unroll
    for (int o = 16; o; o >>= 1) q += __shfl_xor_sync(0xffffffffu, q, o);
    if ((threadIdx.x & 31) == 0) part[8 + w] = q;
    __syncthreads();
    float var = (part[8 + sub * 2] + part[8 + sub * 2 + 1]) * (1.f / 256.f);
    float r = rsqrtf(var + 1e-5f);
    if (valid) {
        float4 gg = *(const float4*)(g + t * 4);
        float4 bt = *(const float4*)(be + t * 4);
        float4 o4;
        o4.x = dx * r * gg.x + bt.x;
        o4.y = dy * r * gg.y + bt.y;
        o4.z = dz * r * gg.z + bt.z;
        o4.w = dw * r * gg.w + bt.w;
        *(float4*)(out + base) = o4;
    }
}

// ---------------- assemble tok = [CLS; x] --------------------------------
__global__ void tok_kernel(const float* __restrict__ CLS,
                           const float* __restrict__ x,
                           float* __restrict__ tok) {
    int r = blockIdx.x;
    int b = r / NT, t = r % NT;
    int c = threadIdx.x;
    tok[(size_t)r * DD + c] = (t == 0)
        ? CLS[(size_t)b * DD + c]
        : x[(size_t)(b * NN + (t - 1)) * DD + c];
}

// ---------------- CLS attention -------------------------------------------
__global__ void cls_attn_kernel(const float* __restrict__ CLS,
                                const float* __restrict__ rkv,
                                const unsigned char* __restrict__ cmask,
                                float* __restrict__ cls2) {
    int b = blockIdx.x;
    __shared__ float sq[8 * 32];
    __shared__ float sp[8 * 160];
    int tid = threadIdx.x, h = tid >> 5, lane = tid & 31;

    sq[h * 32 + lane] = CLS[(size_t)b * DD + h * 32 + lane];
    __syncwarp();
    const float scale = 0.17677669529663687f;
    const float* sqh = sq + h * 32;

    float svals[5];
    float smax = -INFINITY;
#pragma unroll
    for (int j = 0; j < 5; j++) {
        int m = lane + j * 32;
        float s = -INFINITY;
        if (m < NT) {
            const float* kr = rkv + (size_t)(b * NT + m) * 512 + h * 32;
            float s0 = 0.f;
#pragma unroll
            for (int d = 0; d < 32; d++) s0 = fmaf(sqh[d], kr[d], s0);
            s = s0 * scale;
            if (cmask[(size_t)b * NT + m]) s = -INFINITY;
        }
        svals[j] = s;
        smax = fmaxf(smax, s);
    }
#pragma unroll
    for (int o = 16; o; o >>= 1)
        smax = fmaxf(smax, __shfl_xor_sync(0xffffffffu, smax, o));

    float ssum = 0.f;
#pragma unroll
    for (int j = 0; j < 5; j++) {
        float p = __expf(svals[j] - smax);
        ssum += p;
        sp[h * 160 + lane + j * 32] = p;
    }
#pragma unroll
    for (int o = 16; o; o >>= 1)
        ssum += __shfl_xor_sync(0xffffffffu, ssum, o);
    __syncwarp();

    float inv = 1.f / ssum;
    float acc = 0.f;
    for (int m = 0; m < NT; m++)
        acc = fmaf(sp[h * 160 + m],
                   rkv[(size_t)(b * NT + m) * 512 + 256 + h * 32 + lane], acc);
    cls2[(size_t)b * DD + h * 32 + lane] = acc * inv;
}

// ---------------- launch --------------------------------------------------
extern "C" void kernel_launch(void* const* d_in, const int* in_sizes, int n_in,
                              void* d_out, int out_size) {
    const float* node_x   = (const float*)d_in[0];
    const float* edge_x   = (const float*)d_in[1];
    const float* CLS      = (const float*)d_in[2];
    const unsigned char* nmask = (const unsigned char*)d_in[3];
    const unsigned char* cmask = (const unsigned char*)d_in[4];
    const float* w_qkv    = (const float*)d_in[5];
    const float* b_qkv    = (const float*)d_in[6];
    const float* w_kve    = (const float*)d_in[7];
    const float* b_kve    = (const float*)d_in[8];
    const float* w1       = (const float*)d_in[9];
    const float* b1       = (const float*)d_in[10];
    const float* w2       = (const float*)d_in[11];
    const float* b2       = (const float*)d_in[12];
    const float* g1       = (const float*)d_in[13];
    const float* be1      = (const float*)d_in[14];
    const float* g2       = (const float*)d_in[15];
    const float* be2      = (const float*)d_in[16];
    const float* ro_w_kv  = (const float*)d_in[17];
    const float* ro_b_kv  = (const float*)d_in[18];
    const float* ro_w1    = (const float*)d_in[19];
    const float* ro_b1    = (const float*)d_in[20];
    const float* ro_w2    = (const float*)d_in[21];
    const float* ro_b2    = (const float*)d_in[22];
    const float* ro_g1    = (const float*)d_in[23];
    const float* ro_be1   = (const float*)d_in[24];
    const float* ro_g2    = (const float*)d_in[25];
    const float* ro_be2   = (const float*)d_in[26];

    float* out_x = (float*)d_out;
    float* out_c = out_x + (size_t)BB * NN * DD;

    float *p_qkv, *p_kve, *p_attn, *p_x1, *p_h1, *p_ff, *p_tok, *p_rkv;
    float *p_cls2, *p_c1, *p_ch1, *p_cff;
    __nv_bfloat16 *whi, *wlo;
    cudaGetSymbolAddress((void**)&p_qkv,  g_qkv);
    cudaGetSymbolAddress((void**)&p_kve,  g_kve);
    cudaGetSymbolAddress((void**)&p_attn, g_attn);
    cudaGetSymbolAddress((void**)&p_x1,   g_x1);
    cudaGetSymbolAddress((void**)&p_h1,   g_h1);
    cudaGetSymbolAddress((void**)&p_ff,   g_ff);
    cudaGetSymbolAddress((void**)&p_tok,  g_tok);
    cudaGetSymbolAddress((void**)&p_rkv,  g_rkv);
    cudaGetSymbolAddress((void**)&p_cls2, g_cls2);
    cudaGetSymbolAddress((void**)&p_c1,   g_c1);
    cudaGetSymbolAddress((void**)&p_ch1,  g_ch1);
    cudaGetSymbolAddress((void**)&p_cff,  g_cff);
    cudaGetSymbolAddress((void**)&whi,    g_whi);
    cudaGetSymbolAddress((void**)&wlo,    g_wlo);

    const int gemm_smem = 4 * 128 * GST * (int)sizeof(__nv_bfloat16);  // 73728
    cudaFuncSetAttribute(gemm_mma<false>, cudaFuncAttributeMaxDynamicSharedMemorySize, gemm_smem);
    cudaFuncSetAttribute(gemm_mma<true>,  cudaFuncAttributeMaxDynamicSharedMemorySize, gemm_smem);
    cudaFuncSetAttribute(attn_mma, cudaFuncAttributeMaxDynamicSharedMemorySize, ATT_SMEM);

    // fused weight conversion (single launch)
    conv_all<<<(W_TOTAL + 255) / 256, 256>>>(w_qkv, w_kve, w1, w2, ro_w_kv, ro_w1, ro_w2, whi, wlo);

    // projections
    gemm_mma<false><<<dim3(6, 64),  256, gemm_smem>>>(node_x, whi + OFF_QKV, wlo + OFF_QKV, b_qkv, p_qkv, BB * NN, 768);
    gemm_mma<false><<<dim3(4, 128), 256, gemm_smem>>>(edge_x, whi + OFF_KVE, wlo + OFF_KVE, b_kve, p_kve, BB * EE, 512);

    // attention (tensor cores)
    attn_mma<<<dim3(16, BB), 256, ATT_SMEM>>>(p_qkv, p_kve, nmask, p_attn);

    ln4<<<BB * NN / 4, 256>>>(node_x, p_attn, g1, be1, p_x1, BB * NN);
    gemm_mma<true ><<<dim3(2, 64), 256, gemm_smem>>>(p_x1, whi + OFF_W1, wlo + OFF_W1, b1, p_h1, BB * NN, 256);
    gemm_mma<false><<<dim3(2, 64), 256, gemm_smem>>>(p_h1, whi + OFF_W2, wlo + OFF_W2, b2, p_ff, BB * NN, 256);
    ln4<<<BB * NN / 4, 256>>>(p_x1, p_ff, g2, be2, out_x, BB * NN);

    // readout
    tok_kernel<<<BB * NT, 256>>>(CLS, out_x, p_tok);
    gemm_mma<false><<<dim3(4, 65), 256, gemm_smem>>>(p_tok, whi + OFF_ROKV, wlo + OFF_ROKV, ro_b_kv, p_rkv, BB * NT, 512);
    cls_attn_kernel<<<BB, 256>>>(CLS, p_rkv, cmask, p_cls2);
    ln4<<<BB / 4, 256>>>(CLS, p_cls2, ro_g1, ro_be1, p_c1, BB);
    gemm_mma<true ><<<dim3(2, 1), 256, gemm_smem>>>(p_c1,  whi + OFF_ROW1, wlo + OFF_ROW1, ro_b1, p_ch1, BB, 256);
    gemm_mma<false><<<dim3(2, 1), 256, gemm_smem>>>(p_ch1, whi + OFF_ROW2, wlo + OFF_ROW2, ro_b2, p_cff, BB, 256);
    ln4<<<BB / 4, 256>>>(p_c1, p_cff, ro_g2, ro_be2, out_c, BB);
}